// round 3
// baseline (speedup 1.0000x reference)
#include <cuda_runtime.h>
#include <math.h>

#define HID 512
#define QD 32
#define OFFN 496
#define NB 148
#define NT 256

// ---------------- scratch (device globals) ----------------------------------
__device__ float d_h1[HID], d_g1[HID], d_h2[HID], d_g2[HID], d_h3[HID];
__device__ float d_A1[HID * QD];     // diag(s1) W1                [512,32]
__device__ float d_M1[HID * QD];     // diag(s2) W2 A1             [512,32]
__device__ float d_M2[HID * QD];     // diag(s3) W3 M1             [512,32]
__device__ float d_Bo[QD * HID];     // Bo[j,c] = sum_{i>j} qt[i] Wo[p(i,j),c]
__device__ float d_wvec[HID];        // w = M2 @ q_t               [512]
__device__ float d_v[QD + OFFN];     // v = dh4 @ w                [528]
__device__ float d_F[QD * QD];       // F = Beff @ M2              [32,32]
__device__ float d_ldiag[QD], d_loff[OFFN], d_gvec[QD];

// ---------------- grid barrier ----------------------------------------------
__device__ unsigned int g_arrive = 0;
__device__ volatile unsigned int g_gen = 0;

__device__ __forceinline__ void grid_sync() {
    __threadfence();
    __syncthreads();
    if (threadIdx.x == 0) {
        unsigned int gen = g_gen;
        if (atomicAdd(&g_arrive, 1u) == NB - 1) {
            g_arrive = 0;
            __threadfence();
            g_gen = gen + 1;
        } else {
            while (g_gen == gen) { }
        }
    }
    __syncthreads();
}

__device__ __forceinline__ float sigm(float x) { return 1.f / (1.f + expf(-x)); }

// warp dot of length 512: W via read-only path (true const param),
// x via coherent plain loads (intra-launch scratch). Result in all lanes.
__device__ __forceinline__ float wdot512(const float* __restrict__ W,
                                         const float* __restrict__ x, int lane) {
    const float4* W4 = (const float4*)W;
    const float4* x4 = (const float4*)x;
    float4 wa = __ldg(W4 + lane);      float4 xa = x4[lane];
    float4 wb = __ldg(W4 + lane + 32); float4 xb = x4[lane + 32];
    float4 wc = __ldg(W4 + lane + 64); float4 xc = x4[lane + 64];
    float4 wd = __ldg(W4 + lane + 96); float4 xd = x4[lane + 96];
    float a0 = wa.x * xa.x + wa.y * xa.y + wa.z * xa.z + wa.w * xa.w;
    float a1 = wb.x * xb.x + wb.y * xb.y + wb.z * xb.z + wb.w * xb.w;
    float a2 = wc.x * xc.x + wc.y * xc.y + wc.z * xc.z + wc.w * xc.w;
    float a3 = wd.x * xd.x + wd.y * xd.y + wd.z * xd.z + wd.w * xd.w;
    float acc = (a0 + a1) + (a2 + a3);
#pragma unroll
    for (int o = 16; o; o >>= 1) acc += __shfl_xor_sync(0xffffffffu, acc, o);
    return acc;
}

// block computes 8 rows of Y = diag(s(hvec)) * (W @ M); M is [512,32] scratch.
// Warp w covers c in [64w, 64w+64). Optional epilogue: wvec_out[r] = Y_row . qt
__device__ __forceinline__ void gemm8(const float* __restrict__ W, int rbase,
                                      const float* __restrict__ M,
                                      const float* __restrict__ hvec,
                                      float* __restrict__ Y,
                                      const float* __restrict__ qt,
                                      float* __restrict__ wvec_out,
                                      float* __restrict__ shm) {
    int tid = threadIdx.x;
    int lane = tid & 31, w = tid >> 5;
    float acc[8];
#pragma unroll
    for (int i = 0; i < 8; i++) acc[i] = 0.f;
    int base = w * 16;
#pragma unroll
    for (int t = 0; t < 16; t++) {
        int c4 = base + t;
        int c = c4 * 4;
        float m0 = M[(c + 0) * QD + lane];
        float m1 = M[(c + 1) * QD + lane];
        float m2 = M[(c + 2) * QD + lane];
        float m3 = M[(c + 3) * QD + lane];
#pragma unroll
        for (int i = 0; i < 8; i++) {
            float4 v = __ldg(((const float4*)(W + (rbase + i) * HID)) + c4);
            acc[i] += v.x * m0 + v.y * m1 + v.z * m2 + v.w * m3;
        }
    }
#pragma unroll
    for (int i = 0; i < 8; i++) shm[(w * 8 + i) * 33 + lane] = acc[i];
    __syncthreads();
    {
        int i = tid >> 5, j = lane;          // i = row 0..7, j = col
        float s = 0.f;
#pragma unroll
        for (int u = 0; u < 8; u++) s += shm[(u * 8 + i) * 33 + j];
        int r = rbase + i;
        float h = hvec[r];
        float val = h * (1.f - h) * s;
        Y[r * QD + j] = val;
        if (wvec_out) {
            float contrib = val * __ldg(qt + j);
#pragma unroll
            for (int o = 16; o; o >>= 1)
                contrib += __shfl_xor_sync(0xffffffffu, contrib, o);
            if (j == 0) wvec_out[r] = contrib;
        }
    }
    __syncthreads();
}

// ---------------- the one kernel ---------------------------------------------
__global__ __launch_bounds__(NT)
void fused(const float* __restrict__ q, const float* __restrict__ q_t,
           const float* __restrict__ q_tt,
           const float* __restrict__ W1, const float* __restrict__ b1,
           const float* __restrict__ W2, const float* __restrict__ b2,
           const float* __restrict__ W3, const float* __restrict__ b3,
           const float* __restrict__ Wd, const float* __restrict__ bd,
           const float* __restrict__ Wo, const float* __restrict__ bo,
           const float* __restrict__ Wg1, const float* __restrict__ bg1,
           const float* __restrict__ Wg2, const float* __restrict__ bg2,
           const float* __restrict__ Wg3, const float* __restrict__ bg3,
           float* __restrict__ out) {
    __shared__ float shm[2304];
    int b = blockIdx.x, tid = threadIdx.x;
    int lane = tid & 31, w = tid >> 5;

    // ======== S1: Bo, h1, g1 ================================================
    {
        if (tid < QD) shm[tid] = __ldg(q_t + tid);
        __syncthreads();
        int t = b * NT + tid;
        if (t < QD * HID) {                               // Bo
            int a = t >> 9, c = t & 511;
            float acc = 0.f;
            for (int i = a + 1; i < QD; i++)
                acc += shm[i] * __ldg(Wo + (((i * (i - 1)) >> 1) + a) * HID + c);
            d_Bo[t] = acc;
        } else if (t < QD * HID + HID) {                  // h1
            int r = t - QD * HID;
            float acc = __ldg(b1 + r);
            const float4* w4 = (const float4*)(W1 + r * QD);
            const float4* q4 = (const float4*)q;
#pragma unroll
            for (int k = 0; k < 8; k++) {
                float4 a = __ldg(w4 + k), bb = __ldg(q4 + k);
                acc += a.x * bb.x + a.y * bb.y + a.z * bb.z + a.w * bb.w;
            }
            d_h1[r] = sigm(acc);
        } else if (t < QD * HID + 2 * HID) {              // g1
            int r = t - QD * HID - HID;
            float acc = __ldg(bg1 + r);
            const float4* w4 = (const float4*)(Wg1 + r * QD);
            const float4* q4 = (const float4*)q;
#pragma unroll
            for (int k = 0; k < 8; k++) {
                float4 a = __ldg(w4 + k), bb = __ldg(q4 + k);
                acc += a.x * bb.x + a.y * bb.y + a.z * bb.z + a.w * bb.w;
            }
            d_g1[r] = sigm(acc);
        }
        __syncthreads();   // shm reused later
    }
    grid_sync();

    // ======== S2: h2, g2, A1 ================================================
    {
        int gw = b * 8 + w;
        if (gw < HID) {
            float acc = wdot512(W2 + gw * HID, d_h1, lane);
            if (lane == 0) d_h2[gw] = sigm(acc + __ldg(b2 + gw));
        } else if (gw < 2 * HID) {
            int r = gw - HID;
            float acc = wdot512(Wg2 + r * HID, d_g1, lane);
            if (lane == 0) d_g2[r] = sigm(acc + __ldg(bg2 + r));
        } else {                                          // A1 (float4)
            int t4 = (gw - 2 * HID) * 32 + lane;          // 0..5119, need 4096
            if (t4 < HID * QD / 4) {
                float4 wv = __ldg(((const float4*)W1) + t4);
                float h = d_h1[t4 >> 3];
                float s = h * (1.f - h);
                ((float4*)d_A1)[t4] =
                    make_float4(s * wv.x, s * wv.y, s * wv.z, s * wv.w);
            }
        }
    }
    grid_sync();

    // ======== S3: M1 = diag(s2) W2 A1 ; h3 ==================================
    if (b < 64) {
        gemm8(W2, b * 8, d_A1, d_h2, d_M1, nullptr, nullptr, shm);
    } else if (b < 128) {
        int r = (b - 64) * 8 + w;                         // 0..511
        float acc = wdot512(W3 + r * HID, d_h2, lane);
        if (lane == 0) d_h3[r] = sigm(acc + __ldg(b3 + r));
    }
    grid_sync();

    // ======== S4: M2 (+w), loff, ldiag, gvec ================================
    if (b < 64) {
        gemm8(W3, b * 8, d_M1, d_h3, d_M2, q_t, d_wvec, shm);
    } else if (b < 126) {
        int p = (b - 64) * 8 + w;                         // 0..495
        float acc = wdot512(Wo + p * HID, d_h3, lane);
        if (lane == 0) d_loff[p] = acc + __ldg(bo + p);
    } else if (b < 130) {
        int i = (b - 126) * 8 + w;                        // 0..31
        float acc = wdot512(Wd + i * HID, d_h3, lane);
        if (lane == 0) d_ldiag[i] = expf(acc + __ldg(bd + i));
    } else if (b < 134) {
        int i = (b - 130) * 8 + w;                        // 0..31
        float acc = wdot512(Wg3 + i * HID, d_g2, lane);
        if (lane == 0) d_gvec[i] = acc + __ldg(bg3 + i);
    }
    grid_sync();

    // ======== S5: F = Beff @ M2 ; v = dh4 @ w ===============================
    if (b < 8) {
        // F rows rbase..rbase+3 ; Beff[j,c] = qt[j]*ldiag[j]*Wd[j,c] + Bo[j,c]
        float* sp = shm;                 // [8][4][33]
        float* sqld = shm + 1056;        // [4]
        int rbase = b * 4;
        if (tid < 4) sqld[tid] = __ldg(q_t + rbase + tid) * d_ldiag[rbase + tid];
        __syncthreads();
        float q0 = sqld[0], q1 = sqld[1], q2 = sqld[2], q3 = sqld[3];
        const float4* Wd0 = (const float4*)(Wd + (rbase + 0) * HID);
        const float4* Wd1 = (const float4*)(Wd + (rbase + 1) * HID);
        const float4* Wd2 = (const float4*)(Wd + (rbase + 2) * HID);
        const float4* Wd3 = (const float4*)(Wd + (rbase + 3) * HID);
        const float4* Bo0 = (const float4*)(d_Bo + (rbase + 0) * HID);
        const float4* Bo1 = (const float4*)(d_Bo + (rbase + 1) * HID);
        const float4* Bo2 = (const float4*)(d_Bo + (rbase + 2) * HID);
        const float4* Bo3 = (const float4*)(d_Bo + (rbase + 3) * HID);
        float a0 = 0.f, a1 = 0.f, a2 = 0.f, a3 = 0.f;
        int base = w * 16;
#pragma unroll
        for (int t = 0; t < 16; t++) {
            int c4 = base + t;
            float4 wv0 = __ldg(Wd0 + c4); float4 bv0 = Bo0[c4];
            float4 wv1 = __ldg(Wd1 + c4); float4 bv1 = Bo1[c4];
            float4 wv2 = __ldg(Wd2 + c4); float4 bv2 = Bo2[c4];
            float4 wv3 = __ldg(Wd3 + c4); float4 bv3 = Bo3[c4];
            int c = c4 * 4;
            float m0 = d_M2[(c + 0) * QD + lane];
            float m1 = d_M2[(c + 1) * QD + lane];
            float m2 = d_M2[(c + 2) * QD + lane];
            float m3 = d_M2[(c + 3) * QD + lane];
            a0 += (q0 * wv0.x + bv0.x) * m0 + (q0 * wv0.y + bv0.y) * m1 +
                  (q0 * wv0.z + bv0.z) * m2 + (q0 * wv0.w + bv0.w) * m3;
            a1 += (q1 * wv1.x + bv1.x) * m0 + (q1 * wv1.y + bv1.y) * m1 +
                  (q1 * wv1.z + bv1.z) * m2 + (q1 * wv1.w + bv1.w) * m3;
            a2 += (q2 * wv2.x + bv2.x) * m0 + (q2 * wv2.y + bv2.y) * m1 +
                  (q2 * wv2.z + bv2.z) * m2 + (q2 * wv2.w + bv2.w) * m3;
            a3 += (q3 * wv3.x + bv3.x) * m0 + (q3 * wv3.y + bv3.y) * m1 +
                  (q3 * wv3.z + bv3.z) * m2 + (q3 * wv3.w + bv3.w) * m3;
        }
        sp[(w * 4 + 0) * 33 + lane] = a0;
        sp[(w * 4 + 1) * 33 + lane] = a1;
        sp[(w * 4 + 2) * 33 + lane] = a2;
        sp[(w * 4 + 3) * 33 + lane] = a3;
        __syncthreads();
        if (tid < 128) {
            int i = tid >> 5, j = tid & 31;
            float s = 0.f;
#pragma unroll
            for (int u = 0; u < 8; u++) s += sp[(u * 4 + i) * 33 + j];
            d_F[(rbase + i) * QD + j] = s;
        }
    } else if (b < 74) {
        int r = (b - 8) * 8 + w;                          // 0..527
        if (r < QD) {
            float acc = wdot512(Wd + r * HID, d_wvec, lane);
            if (lane == 0) d_v[r] = d_ldiag[r] * acc;
        } else {
            int p = r - QD;
            float acc = wdot512(Wo + p * HID, d_wvec, lane);
            if (lane == 0) d_v[r] = acc;
        }
    }
    grid_sync();

    // ======== S6: final assembly (block 0) ==================================
    // tau = c1 + c2 + 0.5*c3 - 0.5*c4 + g   (comp_5 == comp_3)
    if (b == 0) {
        float* sL = shm;            // [32][33]
        float* sD = shm + 1056;     // [32][33]
        float* sm = shm + 2112;     // sqt[32], sqtt[32], sLTqt[32], su1[32], su2[32]
        float* sqt = sm, *sqtt = sm + 32, *sLTqt = sm + 64,
             * su1 = sm + 96, *su2 = sm + 128;
        __syncthreads();            // shm reuse safety (F stage above used shm)
        if (tid < QD) { sqt[tid] = __ldg(q_t + tid); sqtt[tid] = __ldg(q_tt + tid); }
        __syncthreads();
        for (int t = tid; t < QD * QD; t += NT) {
            int i = t >> 5, j = t & 31;
            float lv = 0.f, dv = 0.f;
            if (i == j) { lv = d_ldiag[i]; dv = d_v[i]; }
            else if (i > j) {
                int p = ((i * (i - 1)) >> 1) + j;
                lv = d_loff[p]; dv = d_v[QD + p];
            }
            sL[i * 33 + j] = lv; sD[i * 33 + j] = dv;
        }
        __syncthreads();
        if (tid < QD) {
            int j = tid;
            float a = 0.f, bb = 0.f, c = 0.f;
#pragma unroll
            for (int i = 0; i < QD; i++) {
                a  += sL[i * 33 + j] * sqt[i];
                bb += sL[i * 33 + j] * sqtt[i];
                c  += sD[i * 33 + j] * sqt[i];
            }
            sLTqt[j] = a; su1[j] = bb; su2[j] = c;
        }
        __syncthreads();
        if (tid < QD) {
            int i = tid;
            float acc = d_gvec[i];
#pragma unroll
            for (int j = 0; j < QD; j++) {
                acc += sL[i * 33 + j] * (su1[j] + su2[j]) +
                       0.5f * (sD[i * 33 + j] - d_F[i * QD + j]) * sLTqt[j];
            }
            out[i] = acc;
        }
    }
}

// ---------------- launch ------------------------------------------------------
extern "C" void kernel_launch(void* const* d_in, const int* in_sizes, int n_in,
                              void* d_out, int out_size) {
    const float* q    = (const float*)d_in[0];
    const float* q_t  = (const float*)d_in[1];
    const float* q_tt = (const float*)d_in[2];
    const float* W1   = (const float*)d_in[3];
    const float* b1   = (const float*)d_in[4];
    const float* W2   = (const float*)d_in[5];
    const float* b2   = (const float*)d_in[6];
    const float* W3   = (const float*)d_in[7];
    const float* b3   = (const float*)d_in[8];
    const float* Wd   = (const float*)d_in[9];
    const float* bd   = (const float*)d_in[10];
    const float* Wo   = (const float*)d_in[11];
    const float* bo   = (const float*)d_in[12];
    const float* Wg1  = (const float*)d_in[13];
    const float* bg1  = (const float*)d_in[14];
    const float* Wg2  = (const float*)d_in[15];
    const float* bg2  = (const float*)d_in[16];
    const float* Wg3  = (const float*)d_in[17];
    const float* bg3  = (const float*)d_in[18];
    float* out = (float*)d_out;

    fused<<<NB, NT>>>(q, q_t, q_tt, W1, b1, W2, b2, W3, b3, Wd, bd, Wo, bo,
                      Wg1, bg1, Wg2, bg2, Wg3, bg3, out);
}

// round 4
// speedup vs baseline: 1.4623x; 1.4623x over previous
#include <cuda_runtime.h>
#include <math.h>

#define HID 512
#define QD 32
#define OFFN 496
#define NB 148
#define NT 512
#define NWARP 16

// ---------------- scratch (device globals) ----------------------------------
__device__ float d_h1[HID], d_g1[HID], d_h2[HID], d_g2[HID], d_h3[HID];
__device__ float d_A1[HID * QD];     // diag(s1) W1                [512,32]
__device__ float d_M1[HID * QD];     // diag(s2) W2 A1             [512,32]
__device__ float d_M2[HID * QD];     // diag(s3) W3 M1             [512,32]
__device__ float d_Bo[QD * HID];     // Bo[a,c] = sum_{i>a} qt[i] Wo[p(i,a),c]
__device__ float d_wvec[HID];        // w = M2 @ q_t               [512]
__device__ float d_v[QD + OFFN];     // v = dh4 @ w                [528]
__device__ float d_F[QD * QD];       // F = Beff @ M2              [32,32]
__device__ float d_ldiag[QD], d_loff[OFFN], d_gvec[QD];

// ---------------- grid barrier ----------------------------------------------
__device__ unsigned int g_arrive = 0;
__device__ volatile unsigned int g_gen = 0;

__device__ __forceinline__ void grid_sync() {
    __threadfence();
    __syncthreads();
    if (threadIdx.x == 0) {
        unsigned int gen = g_gen;
        if (atomicAdd(&g_arrive, 1u) == NB - 1) {
            g_arrive = 0;
            __threadfence();
            g_gen = gen + 1;
        } else {
            while (g_gen == gen) { }
        }
    }
    __syncthreads();
}

__device__ __forceinline__ float sigm(float x) { return 1.f / (1.f + expf(-x)); }

// warp dot of length 512; W read-only path, x coherent. Result in all lanes.
__device__ __forceinline__ float wdot512(const float* __restrict__ W,
                                         const float* __restrict__ x, int lane) {
    const float4* W4 = (const float4*)W;
    const float4* x4 = (const float4*)x;
    float4 wa = __ldg(W4 + lane);      float4 xa = x4[lane];
    float4 wb = __ldg(W4 + lane + 32); float4 xb = x4[lane + 32];
    float4 wc = __ldg(W4 + lane + 64); float4 xc = x4[lane + 64];
    float4 wd = __ldg(W4 + lane + 96); float4 xd = x4[lane + 96];
    float a0 = wa.x * xa.x + wa.y * xa.y + wa.z * xa.z + wa.w * xa.w;
    float a1 = wb.x * xb.x + wb.y * xb.y + wb.z * xb.z + wb.w * xb.w;
    float a2 = wc.x * xc.x + wc.y * xc.y + wc.z * xc.z + wc.w * xc.w;
    float a3 = wd.x * xd.x + wd.y * xd.y + wd.z * xd.z + wd.w * xd.w;
    float acc = (a0 + a1) + (a2 + a3);
#pragma unroll
    for (int o = 16; o; o >>= 1) acc += __shfl_xor_sync(0xffffffffu, acc, o);
    return acc;
}

// GEMM core after sw[] is staged with 4 rows (4*512 floats).
// Computes Y[rbase+i][j] = scale_i * sum_c sw[i*512+c]*M[c*32+j], 16-way K-split.
// hvec != null: scale_i = s(hvec[r]) (sigmoid deriv). wvec_out != null:
// also writes wvec_out[r] = Y_row . qt.
__device__ __forceinline__ void gemm4_core(int rbase,
                                           const float* __restrict__ M,
                                           const float* __restrict__ hvec,
                                           float* __restrict__ Y,
                                           const float* __restrict__ qt,
                                           float* __restrict__ wvec_out,
                                           const float* __restrict__ sw,
                                           float* __restrict__ sp) {
    int tid = threadIdx.x;
    int lane = tid & 31, w = tid >> 5;
    const float4* sw4 = (const float4*)sw;
    float a0 = 0.f, a1 = 0.f, a2 = 0.f, a3 = 0.f;
#pragma unroll
    for (int t = 0; t < 8; t++) {
        int c4 = w * 8 + t;
        int c = c4 * 4;
        float m0 = M[(c + 0) * QD + lane];
        float m1 = M[(c + 1) * QD + lane];
        float m2 = M[(c + 2) * QD + lane];
        float m3 = M[(c + 3) * QD + lane];
        float4 v0 = sw4[c4];
        float4 v1 = sw4[128 + c4];
        float4 v2 = sw4[256 + c4];
        float4 v3 = sw4[384 + c4];
        a0 += v0.x * m0 + v0.y * m1 + v0.z * m2 + v0.w * m3;
        a1 += v1.x * m0 + v1.y * m1 + v1.z * m2 + v1.w * m3;
        a2 += v2.x * m0 + v2.y * m1 + v2.z * m2 + v2.w * m3;
        a3 += v3.x * m0 + v3.y * m1 + v3.z * m2 + v3.w * m3;
    }
    sp[(w * 4 + 0) * 33 + lane] = a0;
    sp[(w * 4 + 1) * 33 + lane] = a1;
    sp[(w * 4 + 2) * 33 + lane] = a2;
    sp[(w * 4 + 3) * 33 + lane] = a3;
    __syncthreads();
    if (tid < 128) {
        int i = tid >> 5, j = lane;
        float s = 0.f;
#pragma unroll
        for (int u = 0; u < 16; u++) s += sp[(u * 4 + i) * 33 + j];
        int r = rbase + i;
        float val = s;
        if (hvec) {
            float h = hvec[r];
            val = h * (1.f - h) * s;
        }
        Y[r * QD + j] = val;
        if (wvec_out) {
            float contrib = val * __ldg(qt + j);
#pragma unroll
            for (int o = 16; o; o >>= 1)
                contrib += __shfl_xor_sync(0xffffffffu, contrib, o);
            if (j == 0) wvec_out[r] = contrib;
        }
    }
    __syncthreads();
}

// ---------------- the one kernel ---------------------------------------------
__global__ __launch_bounds__(NT)
void fused(const float* __restrict__ q, const float* __restrict__ q_t,
           const float* __restrict__ q_tt,
           const float* __restrict__ W1, const float* __restrict__ b1,
           const float* __restrict__ W2, const float* __restrict__ b2,
           const float* __restrict__ W3, const float* __restrict__ b3,
           const float* __restrict__ Wd, const float* __restrict__ bd,
           const float* __restrict__ Wo, const float* __restrict__ bo,
           const float* __restrict__ Wg1, const float* __restrict__ bg1,
           const float* __restrict__ Wg2, const float* __restrict__ bg2,
           const float* __restrict__ Wg3, const float* __restrict__ bg3,
           float* __restrict__ out) {
    __shared__ float shm[4288];   // sw[2048] | sp[2112] | misc[128]
    int b = blockIdx.x, tid = threadIdx.x;
    int lane = tid & 31, w = tid >> 5;

    // ======== S1: Bo (32 blocks), h1 (1 block), g1 (1 block) ================
    if (b < 32) {
        int t = b * NT + tid;                   // 0..16383
        int a = t >> 9, c = t & 511;
        float acc = 0.f;
#pragma unroll
        for (int i = 1; i < 32; i++) {
            if (i > a)
                acc += __ldg(q_t + i) *
                       __ldg(Wo + (((i * (i - 1)) >> 1) + a) * HID + c);
        }
        d_Bo[t] = acc;
    } else if (b == 32) {
        int r = tid;                            // 0..511
        float acc = __ldg(b1 + r);
        const float4* w4 = (const float4*)(W1 + r * QD);
        const float4* q4 = (const float4*)q;
#pragma unroll
        for (int k = 0; k < 8; k++) {
            float4 a = __ldg(w4 + k), bb = __ldg(q4 + k);
            acc += a.x * bb.x + a.y * bb.y + a.z * bb.z + a.w * bb.w;
        }
        d_h1[r] = sigm(acc);
    } else if (b == 33) {
        int r = tid;
        float acc = __ldg(bg1 + r);
        const float4* w4 = (const float4*)(Wg1 + r * QD);
        const float4* q4 = (const float4*)q;
#pragma unroll
        for (int k = 0; k < 8; k++) {
            float4 a = __ldg(w4 + k), bb = __ldg(q4 + k);
            acc += a.x * bb.x + a.y * bb.y + a.z * bb.z + a.w * bb.w;
        }
        d_g1[r] = sigm(acc);
    }
    grid_sync();

    // ======== S2: h2 (32 blk), g2 (32 blk), A1 (8 blk) ======================
    if (b < 32) {
        int r = b * NWARP + w;                  // 0..511
        float acc = wdot512(W2 + r * HID, d_h1, lane);
        if (lane == 0) d_h2[r] = sigm(acc + __ldg(b2 + r));
    } else if (b < 64) {
        int r = (b - 32) * NWARP + w;
        float acc = wdot512(Wg2 + r * HID, d_g1, lane);
        if (lane == 0) d_g2[r] = sigm(acc + __ldg(bg2 + r));
    } else if (b < 72) {
        int t4 = (b - 64) * NT + tid;           // 0..4095
        float4 wv = __ldg(((const float4*)W1) + t4);
        float h = d_h1[t4 >> 3];
        float s = h * (1.f - h);
        ((float4*)d_A1)[t4] = make_float4(s * wv.x, s * wv.y, s * wv.z, s * wv.w);
    }
    grid_sync();

    // ======== S3: M1 = diag(s2) W2 A1 (128 blk) ; h3 (20 blk) ===============
    if (b < 128) {
        int rbase = b * 4;
        ((float4*)shm)[tid] = __ldg((const float4*)(W2 + rbase * HID) + tid);
        __syncthreads();
        gemm4_core(rbase, d_A1, d_h2, d_M1, nullptr, nullptr, shm, shm + 2048);
    } else {
        for (int r = (b - 128) * NWARP + w; r < HID; r += 20 * NWARP) {
            float acc = wdot512(W3 + r * HID, d_h2, lane);
            if (lane == 0) d_h3[r] = sigm(acc + __ldg(b3 + r));
        }
    }
    grid_sync();

    // ======== S4: M2 (+wvec) (128 blk) ; loff/ldiag/gvec (20 blk) ===========
    if (b < 128) {
        int rbase = b * 4;
        ((float4*)shm)[tid] = __ldg((const float4*)(W3 + rbase * HID) + tid);
        __syncthreads();
        gemm4_core(rbase, d_M1, d_h3, d_M2, q_t, d_wvec, shm, shm + 2048);
    } else {
        for (int tk = (b - 128) * NWARP + w; tk < OFFN + 2 * QD; tk += 20 * NWARP) {
            if (tk < OFFN) {
                float acc = wdot512(Wo + tk * HID, d_h3, lane);
                if (lane == 0) d_loff[tk] = acc + __ldg(bo + tk);
            } else if (tk < OFFN + QD) {
                int i = tk - OFFN;
                float acc = wdot512(Wd + i * HID, d_h3, lane);
                if (lane == 0) d_ldiag[i] = expf(acc + __ldg(bd + i));
            } else {
                int i = tk - OFFN - QD;
                float acc = wdot512(Wg3 + i * HID, d_g2, lane);
                if (lane == 0) d_gvec[i] = acc + __ldg(bg3 + i);
            }
        }
    }
    grid_sync();

    // ======== S5: F = Beff @ M2 (8 blk) ; v = dh4 @ w (33 blk) ==============
    if (b < 8) {
        int rbase = b * 4;
        if (tid < 4)
            shm[4160 + tid] = __ldg(q_t + rbase + tid) * d_ldiag[rbase + tid];
        __syncthreads();
        int row = tid >> 7, c4l = tid & 127;
        float ql = shm[4160 + row];
        float4 wv = __ldg((const float4*)(Wd + (rbase + row) * HID) + c4l);
        float4 bv = ((const float4*)(d_Bo + (rbase + row) * HID))[c4l];
        ((float4*)shm)[tid] = make_float4(ql * wv.x + bv.x, ql * wv.y + bv.y,
                                          ql * wv.z + bv.z, ql * wv.w + bv.w);
        __syncthreads();
        gemm4_core(rbase, d_M2, nullptr, d_F, nullptr, nullptr, shm, shm + 2048);
    } else if (b < 41) {
        int r = (b - 8) * NWARP + w;            // 0..527
        if (r < QD) {
            float acc = wdot512(Wd + r * HID, d_wvec, lane);
            if (lane == 0) d_v[r] = d_ldiag[r] * acc;
        } else {
            int p = r - QD;
            float acc = wdot512(Wo + p * HID, d_wvec, lane);
            if (lane == 0) d_v[r] = acc;
        }
    }
    grid_sync();

    // ======== S6: final assembly (block 0) ==================================
    // tau = c1 + c2 + 0.5*c3 - 0.5*c4 + g   (comp_5 == comp_3)
    if (b == 0) {
        float* sL = shm;            // [32][33]
        float* sD = shm + 1056;     // [32][33]
        float* sm = shm + 2112;
        float* sqt = sm, *sqtt = sm + 32, *sLTqt = sm + 64,
             * su1 = sm + 96, *su2 = sm + 128;
        if (tid < QD) { sqt[tid] = __ldg(q_t + tid); sqtt[tid] = __ldg(q_tt + tid); }
        __syncthreads();
        for (int t = tid; t < QD * QD; t += NT) {
            int i = t >> 5, j = t & 31;
            float lv = 0.f, dv = 0.f;
            if (i == j) { lv = d_ldiag[i]; dv = d_v[i]; }
            else if (i > j) {
                int p = ((i * (i - 1)) >> 1) + j;
                lv = d_loff[p]; dv = d_v[QD + p];
            }
            sL[i * 33 + j] = lv; sD[i * 33 + j] = dv;
        }
        __syncthreads();
        if (tid < QD) {
            int j = tid;
            float a = 0.f, bb = 0.f, c = 0.f;
#pragma unroll
            for (int i = 0; i < QD; i++) {
                a  += sL[i * 33 + j] * sqt[i];
                bb += sL[i * 33 + j] * sqtt[i];
                c  += sD[i * 33 + j] * sqt[i];
            }
            sLTqt[j] = a; su1[j] = bb; su2[j] = c;
        }
        __syncthreads();
        if (tid < QD) {
            int i = tid;
            float acc = d_gvec[i];
#pragma unroll
            for (int j = 0; j < QD; j++) {
                acc += sL[i * 33 + j] * (su1[j] + su2[j]) +
                       0.5f * (sD[i * 33 + j] - d_F[i * QD + j]) * sLTqt[j];
            }
            out[i] = acc;
        }
    }
}

// ---------------- launch ------------------------------------------------------
extern "C" void kernel_launch(void* const* d_in, const int* in_sizes, int n_in,
                              void* d_out, int out_size) {
    const float* q    = (const float*)d_in[0];
    const float* q_t  = (const float*)d_in[1];
    const float* q_tt = (const float*)d_in[2];
    const float* W1   = (const float*)d_in[3];
    const float* b1   = (const float*)d_in[4];
    const float* W2   = (const float*)d_in[5];
    const float* b2   = (const float*)d_in[6];
    const float* W3   = (const float*)d_in[7];
    const float* b3   = (const float*)d_in[8];
    const float* Wd   = (const float*)d_in[9];
    const float* bd   = (const float*)d_in[10];
    const float* Wo   = (const float*)d_in[11];
    const float* bo   = (const float*)d_in[12];
    const float* Wg1  = (const float*)d_in[13];
    const float* bg1  = (const float*)d_in[14];
    const float* Wg2  = (const float*)d_in[15];
    const float* bg2  = (const float*)d_in[16];
    const float* Wg3  = (const float*)d_in[17];
    const float* bg3  = (const float*)d_in[18];
    float* out = (float*)d_out;

    fused<<<NB, NT>>>(q, q_t, q_tt, W1, b1, W2, b2, W3, b3, Wd, bd, Wo, bo,
                      Wg1, bg1, Wg2, bg2, Wg3, bg3, out);
}